// round 7
// baseline (speedup 1.0000x reference)
#include <cuda_runtime.h>
#include <cstdint>

// ---------------- problem constants ----------------
#define NP   1024
#define DD   1024
#define HID  1536

// ---------------- scratch (device globals; no allocations) ----------------
__device__ float g_pr[NP * DD];
__device__ float g_mag[NP * DD];
__device__ float g_hidden[NP * HID];
__device__ float g_wpart[NP * 16];
__device__ float g_wf[NP];
__device__ float g_psum[NP];
__device__ float g_psumsq[NP];
__device__ float g_stats[2];
__device__ unsigned g_done;   // zero-init; last gemm2 block resets it each run

// ---------------- helpers ----------------
__device__ __forceinline__ float sigmoidf_(float x) { return 1.0f / (1.0f + __expf(-x)); }

__device__ __forceinline__ void mma8(float* c, const uint32_t* a, const uint32_t* b) {
    asm volatile(
        "mma.sync.aligned.m16n8k8.row.col.f32.tf32.tf32.f32 "
        "{%0,%1,%2,%3}, {%4,%5,%6,%7}, {%8,%9}, {%0,%1,%2,%3};\n"
        : "+f"(c[0]), "+f"(c[1]), "+f"(c[2]), "+f"(c[3])
        : "r"(a[0]), "r"(a[1]), "r"(a[2]), "r"(a[3]), "r"(b[0]), "r"(b[1]));
}

__device__ __forceinline__ void cpa16(uint32_t s, const void* g) {
    asm volatile("cp.async.cg.shared.global [%0], [%1], 16;\n" :: "r"(s), "l"(g));
}
__device__ __forceinline__ void cpa_commit() { asm volatile("cp.async.commit_group;\n"); }
__device__ __forceinline__ void cpa_wait2() { asm volatile("cp.async.wait_group 2;\n"); }

// ---- swizzled float-offsets, BK=16 tiles ----
__device__ __forceinline__ int a16(int r, int c) {
    return r * 16 + ((((c >> 2) + (r >> 1)) & 3) << 2) + (c & 3);
}
__device__ __forceinline__ int b16(int r, int c) {
    return r * 64 + ((((c >> 2) + 2 * r) & 15) << 2) + (c & 3);
}

#define A_ELEMS 2048          // 128*16
#define B_ELEMS 1024          // 16*64
#define STAGE   (A_ELEMS + B_ELEMS)           // 3072 floats = 12 KB
#define GSMEM_BYTES (4 * STAGE * 4)           // 49152 = 48 KB; NO static smem allowed on top

// ====================================================================
// Kernel 1: grayscale + patchify + 32x32 DFT + gate + patch sums
// ====================================================================
__global__ __launch_bounds__(256) void k_fft(const float* __restrict__ x,
                                             const float* __restrict__ lf,
                                             const float* __restrict__ mf,
                                             const float* __restrict__ hf) {
    __shared__ float sP[32][33];
    __shared__ float sYre[32][33];
    __shared__ float sYim[32][33];
    __shared__ float twc[32], tws[32];
    __shared__ float rA[8], rB[8];

    const int p = blockIdx.x;
    const int tid = threadIdx.x;
    const int b = p >> 6;
    const int gy = (p >> 3) & 7;
    const int gx = p & 7;

    if (tid < 32) {
        float ang = (float)tid * (1.0f / 16.0f);
        twc[tid] = cospif(ang);
        tws[tid] = sinpif(ang);
    }

    const float* xb = x + (size_t)b * 3 * 65536;
    float ls = 0.f, ls2 = 0.f;
#pragma unroll
    for (int ii = 0; ii < 4; ii++) {
        int idx = tid + ii * 256;
        int i = idx >> 5, j = idx & 31;
        int off = (gy * 32 + i) * 256 + gx * 32 + j;
        float v = 0.299f * xb[off] + 0.587f * xb[65536 + off] + 0.114f * xb[131072 + off];
        sP[i][j] = v;
        g_pr[p * DD + idx] = v;
        ls += v;
        ls2 += v * v;
    }
#pragma unroll
    for (int o = 16; o; o >>= 1) {
        ls += __shfl_xor_sync(0xffffffffu, ls, o);
        ls2 += __shfl_xor_sync(0xffffffffu, ls2, o);
    }
    if ((tid & 31) == 0) { rA[tid >> 5] = ls; rB[tid >> 5] = ls2; }
    __syncthreads();
    if (tid == 0) {
        float a = 0.f, c2 = 0.f;
#pragma unroll
        for (int q = 0; q < 8; q++) { a += rA[q]; c2 += rB[q]; }
        g_psum[p] = a;
        g_psumsq[p] = c2;
    }

#pragma unroll
    for (int ii = 0; ii < 4; ii++) {
        int idx = tid + ii * 256;
        int r = idx >> 5, k = idx & 31;
        float sre = 0.f, sim = 0.f;
        int t = 0;
#pragma unroll
        for (int c = 0; c < 32; c++) {
            float v = sP[r][c];
            sre = fmaf(v, twc[t], sre);
            sim = fmaf(-v, tws[t], sim);
            t = (t + k) & 31;
        }
        sYre[r][k] = sre;
        sYim[r][k] = sim;
    }
    __syncthreads();

    const float sl = sigmoidf_(lf[0]);
    const float sm = sigmoidf_(mf[0]);
    const float sh = sigmoidf_(hf[0]);

#pragma unroll
    for (int ii = 0; ii < 4; ii++) {
        int idx = tid + ii * 256;
        int j = idx >> 5, k = idx & 31;
        float fre = 0.f, fim = 0.f;
        int t = 0;
#pragma unroll
        for (int r = 0; r < 32; r++) {
            float cc = twc[t], ss = tws[t];
            float yre = sYre[r][k], yim = sYim[r][k];
            fre = fmaf(yre, cc, fre);
            fre = fmaf(yim, ss, fre);
            fim = fmaf(yim, cc, fim);
            fim = fmaf(-yre, ss, fim);
            t = (t + j) & 31;
        }
        float mag = sqrtf(fre * fre + fim * fim) * 0.03125f;
        float dy = (float)j - 15.5f, dx = (float)k - 15.5f;
        float r2 = dy * dy + dx * dx;
        float gate = (r2 <= 53.388889f) ? sl : ((r2 <= 213.555556f) ? sm : sh);
        g_mag[p * DD + idx] = mag * gate;
    }
}

// ====================================================================
// GEMM: BM=128, BN=64, BK=16; 256 threads = 8 warps (4m x 2n),
// 4-stage cp.async pipeline (3 tiles in flight), ONE barrier per tile.
// ====================================================================

__device__ __forceinline__ void issue_tile(uint32_t sbase, int buf,
                                           const float* __restrict__ Agm, int lda,
                                           const float* __restrict__ Bgm, int ldb,
                                           int m0, int n0, int k0, int tid) {
    const int ar = tid >> 2, ac = (tid & 3) << 2;
    const int br = tid >> 4, bc = (tid & 15) << 2;
    uint32_t sb = sbase + buf * (STAGE * 4);
    cpa16(sb + a16(ar, ac) * 4,        &Agm[(m0 + ar) * lda + k0 + ac]);
    cpa16(sb + a16(ar + 64, ac) * 4,   &Agm[(m0 + ar + 64) * lda + k0 + ac]);
    cpa16(sb + (A_ELEMS + b16(br, bc)) * 4, &Bgm[(k0 + br) * ldb + n0 + bc]);
}

__device__ __forceinline__ void compute_tile(const float* __restrict__ S,
                                             float acc[2][4][4],
                                             int wm, int wn, int g, int tg) {
    const float* Bc = S + A_ELEMS;
#pragma unroll
    for (int ks = 0; ks < 2; ks++) {
        uint32_t afr[2][4], bfr[4][2];
#pragma unroll
        for (int mt = 0; mt < 2; mt++) {
            int mr = wm * 32 + mt * 16 + g;
            int kk = ks * 8 + tg;
            afr[mt][0] = __float_as_uint(S[a16(mr, kk)]);
            afr[mt][1] = __float_as_uint(S[a16(mr + 8, kk)]);
            afr[mt][2] = __float_as_uint(S[a16(mr, kk + 4)]);
            afr[mt][3] = __float_as_uint(S[a16(mr + 8, kk + 4)]);
        }
#pragma unroll
        for (int nt = 0; nt < 4; nt++) {
            int nc = wn * 32 + nt * 8 + g;
            bfr[nt][0] = __float_as_uint(Bc[b16(ks * 8 + tg, nc)]);
            bfr[nt][1] = __float_as_uint(Bc[b16(ks * 8 + tg + 4, nc)]);
        }
#pragma unroll
        for (int mt = 0; mt < 2; mt++)
#pragma unroll
            for (int nt = 0; nt < 4; nt++) mma8(acc[mt][nt], afr[mt], bfr[nt]);
    }
}

// Kernel 2: hidden = relu(mag @ W1 + b1)   M=1024 N=1536 K=1024  (64 tiles)
__global__ __launch_bounds__(256) void k_gemm1(const float* __restrict__ W1,
                                               const float* __restrict__ b1) {
    extern __shared__ float smem[];
    const int tid = threadIdx.x;
    const int m0 = blockIdx.x * 128, n0 = blockIdx.y * 64;
    const int warp = tid >> 5, lane = tid & 31;
    const int wm = warp & 3, wn = warp >> 2;
    const int g = lane >> 2, tg = lane & 3;

    float acc[2][4][4];
#pragma unroll
    for (int i = 0; i < 2; i++)
#pragma unroll
        for (int j = 0; j < 4; j++)
#pragma unroll
            for (int e = 0; e < 4; e++) acc[i][j][e] = 0.f;

    const uint32_t sbase = (uint32_t)__cvta_generic_to_shared(smem);

#pragma unroll
    for (int t = 0; t < 3; t++) {
        issue_tile(sbase, t, g_mag, 1024, W1, 1536, m0, n0, t * 16, tid);
        cpa_commit();
    }

    for (int kt = 0; kt < 64; kt++) {
        cpa_wait2();
        __syncthreads();
        if (kt + 3 < 64)
            issue_tile(sbase, (kt + 3) & 3, g_mag, 1024, W1, 1536, m0, n0, (kt + 3) * 16, tid);
        cpa_commit();
        compute_tile(smem + (kt & 3) * STAGE, acc, wm, wn, g, tg);
    }

#pragma unroll
    for (int mt = 0; mt < 2; mt++) {
        int row0 = m0 + wm * 32 + mt * 16 + g;
#pragma unroll
        for (int nt = 0; nt < 4; nt++) {
            int col = n0 + wn * 32 + nt * 8 + tg * 2;
            float bb0 = b1[col], bb1 = b1[col + 1];
            float2 o;
            o.x = fmaxf(acc[mt][nt][0] + bb0, 0.f);
            o.y = fmaxf(acc[mt][nt][1] + bb1, 0.f);
            *reinterpret_cast<float2*>(&g_hidden[row0 * 1536 + col]) = o;
            o.x = fmaxf(acc[mt][nt][2] + bb0, 0.f);
            o.y = fmaxf(acc[mt][nt][3] + bb1, 0.f);
            *reinterpret_cast<float2*>(&g_hidden[(row0 + 8) * 1536 + col]) = o;
        }
    }
}

// Kernel 3: attn = sigmoid(hidden @ W2 + b2); rowsum(mag*attn) -> g_wpart;
// last block (ticket) computes per-patch w and global stats.
// ZERO static smem: rank/reduce scratch live in dynamic smem overlay.
__global__ __launch_bounds__(256) void k_gemm2(const float* __restrict__ W2,
                                               const float* __restrict__ b2) {
    extern __shared__ float smem[];
    const int tid = threadIdx.x;
    const int m0 = blockIdx.x * 128, n0 = blockIdx.y * 64;
    const int warp = tid >> 5, lane = tid & 31;
    const int wm = warp & 3, wn = warp >> 2;
    const int g = lane >> 2, tg = lane & 3;

    float acc[2][4][4];
#pragma unroll
    for (int i = 0; i < 2; i++)
#pragma unroll
        for (int j = 0; j < 4; j++)
#pragma unroll
            for (int e = 0; e < 4; e++) acc[i][j][e] = 0.f;

    const uint32_t sbase = (uint32_t)__cvta_generic_to_shared(smem);

#pragma unroll
    for (int t = 0; t < 3; t++) {
        issue_tile(sbase, t, g_hidden, 1536, W2, 1024, m0, n0, t * 16, tid);
        cpa_commit();
    }

    for (int kt = 0; kt < 96; kt++) {
        cpa_wait2();
        __syncthreads();
        if (kt + 3 < 96)
            issue_tile(sbase, (kt + 3) & 3, g_hidden, 1536, W2, 1024, m0, n0, (kt + 3) * 16, tid);
        cpa_commit();
        compute_tile(smem + (kt & 3) * STAGE, acc, wm, wn, g, tg);
    }
    __syncthreads();   // all compute done; smem free for overlays below

    // smem overlays (dynamic region, no static smem):
    float*    sRow  = smem;                               // [0,256): 128 rows x 2
    unsigned* sRank = reinterpret_cast<unsigned*>(smem + 256);
    float*    s_ra  = smem + 272;                         // [272,280)
    float*    s_rb  = smem + 280;                         // [280,288)

    // epilogue: sigmoid, multiply by mag, per-row partial sums
    float rs[2][2] = {{0.f, 0.f}, {0.f, 0.f}};
#pragma unroll
    for (int mt = 0; mt < 2; mt++) {
        int row0 = m0 + wm * 32 + mt * 16 + g;
#pragma unroll
        for (int nt = 0; nt < 4; nt++) {
            int col = n0 + wn * 32 + nt * 8 + tg * 2;
            float bb0 = b2[col], bb1 = b2[col + 1];
            rs[mt][0] += g_mag[row0 * 1024 + col]           * sigmoidf_(acc[mt][nt][0] + bb0);
            rs[mt][0] += g_mag[row0 * 1024 + col + 1]       * sigmoidf_(acc[mt][nt][1] + bb1);
            rs[mt][1] += g_mag[(row0 + 8) * 1024 + col]     * sigmoidf_(acc[mt][nt][2] + bb0);
            rs[mt][1] += g_mag[(row0 + 8) * 1024 + col + 1] * sigmoidf_(acc[mt][nt][3] + bb1);
        }
    }
#pragma unroll
    for (int mt = 0; mt < 2; mt++)
#pragma unroll
        for (int hh = 0; hh < 2; hh++) {
            float v = rs[mt][hh];
            v += __shfl_xor_sync(0xffffffffu, v, 1);
            v += __shfl_xor_sync(0xffffffffu, v, 2);
            if (tg == 0) sRow[(wm * 32 + mt * 16 + hh * 8 + g) * 2 + wn] = v;
        }
    __syncthreads();
    if (tid < 128) g_wpart[(m0 + tid) * 16 + blockIdx.y] = sRow[tid * 2] + sRow[tid * 2 + 1];

    // ---- last-block stats: write -> fence -> barrier -> ticket -> barrier ----
    __threadfence();
    __syncthreads();
    if (tid == 0) sRank[0] = atomicAdd(&g_done, 1u);
    __syncthreads();
    if (sRank[0] == 127u) {        // grid is (8,16) = 128 blocks
        if (tid == 0) g_done = 0u; // reset for next graph replay
        float va = 0.f, vb = 0.f;
#pragma unroll
        for (int q = 0; q < 4; q++) {
            int p = tid + q * 256;
            const float4* w4 = reinterpret_cast<const float4*>(&g_wpart[p * 16]);
            float4 a0 = w4[0], a1 = w4[1], a2 = w4[2], a3 = w4[3];
            float s = (a0.x + a0.y + a0.z + a0.w) + (a1.x + a1.y + a1.z + a1.w)
                    + (a2.x + a2.y + a2.z + a2.w) + (a3.x + a3.y + a3.z + a3.w);
            float wf = 1.0f + s * (1.0f / 1024.0f);
            g_wf[p] = wf;
            va += wf * g_psum[p];
            vb += wf * wf * g_psumsq[p];
        }
#pragma unroll
        for (int o = 16; o; o >>= 1) {
            va += __shfl_xor_sync(0xffffffffu, va, o);
            vb += __shfl_xor_sync(0xffffffffu, vb, o);
        }
        if (lane == 0) { s_ra[warp] = va; s_rb[warp] = vb; }
        __syncthreads();
        if (tid == 0) {
            float xa = 0.f, xb = 0.f;
#pragma unroll
            for (int q = 0; q < 8; q++) { xa += s_ra[q]; xb += s_rb[q]; }
            float mu = xa * (1.0f / 1048576.0f);
            float ex2 = xb * (1.0f / 1048576.0f);
            g_stats[0] = mu;
            g_stats[1] = ex2 - mu * mu;
        }
    }
}

// ====================================================================
// Kernel 4: out = relu(s_c*(x_rec) + o_c) — write-bound
// ====================================================================
__global__ __launch_bounds__(256) void k_final(const float* __restrict__ wproj,
                                               const float* __restrict__ gamma,
                                               const float* __restrict__ beta,
                                               float* __restrict__ out) {
    __shared__ float sS[64], sO[64];
    const int tid = threadIdx.x;
    if (tid < 64) {
        float mu = g_stats[0], var = g_stats[1];
        float wp = wproj[tid];
        float sc = gamma[tid] * wp * rsqrtf(fmaf(wp * wp, var, 1e-5f));
        sS[tid] = sc;
        sO[tid] = beta[tid] - sc * mu;
    }
    __syncthreads();

    const int t = blockIdx.x * 256 + tid;
    const int b = t >> 14;
    const int rem = t & 16383;
    const int h = rem >> 6;
    const int w4 = rem & 63;
    const int p = b * 64 + (h >> 5) * 8 + (w4 >> 3);

    float4 xr = *reinterpret_cast<const float4*>(&g_pr[p * DD + (h & 31) * 32 + (w4 & 7) * 4]);
    const float wf = g_wf[p];
    xr.x *= wf; xr.y *= wf; xr.z *= wf; xr.w *= wf;

    float* ob = out + ((size_t)b << 22) + (h << 8) + (w4 << 2);
#pragma unroll 8
    for (int ch = 0; ch < 64; ch++) {
        float s = sS[ch], o = sO[ch];
        float4 v;
        v.x = fmaxf(fmaf(s, xr.x, o), 0.f);
        v.y = fmaxf(fmaf(s, xr.y, o), 0.f);
        v.z = fmaxf(fmaf(s, xr.z, o), 0.f);
        v.w = fmaxf(fmaf(s, xr.w, o), 0.f);
        *reinterpret_cast<float4*>(ob + ((size_t)ch << 16)) = v;
    }
}

// ====================================================================
extern "C" void kernel_launch(void* const* d_in, const int* in_sizes, int n_in,
                              void* d_out, int out_size) {
    (void)in_sizes; (void)n_in; (void)out_size;
    const float* x     = (const float*)d_in[0];
    const float* W1    = (const float*)d_in[1];
    const float* b1    = (const float*)d_in[2];
    const float* W2    = (const float*)d_in[3];
    const float* b2    = (const float*)d_in[4];
    const float* wproj = (const float*)d_in[5];
    const float* gamma = (const float*)d_in[6];
    const float* beta  = (const float*)d_in[7];
    const float* lf    = (const float*)d_in[8];
    const float* mf    = (const float*)d_in[9];
    const float* hf    = (const float*)d_in[10];
    float* out = (float*)d_out;

    k_fft<<<1024, 256>>>(x, lf, mf, hf);
    k_gemm1<<<dim3(8, 24), 256, GSMEM_BYTES>>>(W1, b1);
    k_gemm2<<<dim3(8, 16), 256, GSMEM_BYTES>>>(W2, b2);
    k_final<<<1024, 256>>>(wproj, gamma, beta, out);
}